// round 13
// baseline (speedup 1.0000x reference)
#include <cuda_runtime.h>
#include <cuda_fp16.h>
#include <cuda_bf16.h>

// ---------------- problem constants ----------------
#define USERNUM   100000
#define ITEMNUM   50000
#define EMBED_D   64
#define NNODES    (USERNUM + ITEMNUM + 1)     // 150001
#define NNZ       4000000
#define BATCHN    4096
#define ROWCAP    128                         // bucket capacity per row (max deg ~66)

// ---------------- scratch (no allocs allowed) ----------------
// fp16 node-embedding buffers: 64 halves = 128 B per row (8 uint4 per row)
__device__ __align__(256) static __half g_x0h[NNODES * EMBED_D];
__device__ __align__(256) static __half g_x1h[NNODES * EMBED_D];
__device__ __align__(256) static __half g_x2h[NNODES * EMBED_D];
// padded bucket CSR: row r owns slots [r*ROWCAP, r*ROWCAP+cnt[r])
// entry = {col:int, weight: half2{v,v} bit-packed}
__device__ __align__(256) static int2  g_cv[(long long)NNODES * ROWCAP];
__device__ static int g_cnt[NNODES];
__device__ __align__(256) static float g_accb[3 * BATCHN * EMBED_D];

// ---------------- helpers ----------------
__device__ __forceinline__ void h8_to_f8(const uint4 h, float* f)
{
    float2 a = __half22float2(*reinterpret_cast<const __half2*>(&h.x));
    float2 b = __half22float2(*reinterpret_cast<const __half2*>(&h.y));
    float2 c = __half22float2(*reinterpret_cast<const __half2*>(&h.z));
    float2 d = __half22float2(*reinterpret_cast<const __half2*>(&h.w));
    f[0] = a.x; f[1] = a.y; f[2] = b.x; f[3] = b.y;
    f[4] = c.x; f[5] = c.y; f[6] = d.x; f[7] = d.y;
}

__device__ __forceinline__ uint4 f8_to_h8(const float* f)
{
    __half2 a = __floats2half2_rn(f[0], f[1]);
    __half2 b = __floats2half2_rn(f[2], f[3]);
    __half2 c = __floats2half2_rn(f[4], f[5]);
    __half2 d = __floats2half2_rn(f[6], f[7]);
    uint4 o;
    o.x = *reinterpret_cast<unsigned*>(&a);
    o.y = *reinterpret_cast<unsigned*>(&b);
    o.z = *reinterpret_cast<unsigned*>(&c);
    o.w = *reinterpret_cast<unsigned*>(&d);
    return o;
}

__device__ __forceinline__ __half2 u2h2(unsigned u)
{
    return *reinterpret_cast<__half2*>(&u);
}

// ---------------- prep: x0h = fp16(concat(ut, it[1:]));  cnt = 0 ----------------
__global__ void k_prep(const float4* __restrict__ ut,
                       const float4* __restrict__ it,
                       uint4* __restrict__ x0h,
                       int* __restrict__ cnt)
{
    int i = blockIdx.x * blockDim.x + threadIdx.x;      // [0, NNODES*8)
    if (i >= NNODES * 8) return;
    if (i < NNODES) cnt[i] = 0;
    int node = i >> 3, q = i & 7;
    const float4* src = (node <= USERNUM)
        ? ut + (long long)node * 16
        : it + (long long)(node - USERNUM) * 16;
    float4 f0 = __ldg(src + q * 2);
    float4 f1 = __ldg(src + q * 2 + 1);
    float f[8] = {f0.x, f0.y, f0.z, f0.w, f1.x, f1.y, f1.z, f1.w};
    x0h[i] = f8_to_h8(f);
}

// ---------------- bucket fill: 4 edges/thread, vectorized streams ----------
__global__ void k_fill(const int4*   __restrict__ rows4,
                       const int4*   __restrict__ cols4,
                       const float4* __restrict__ vals4,
                       int* __restrict__ cnt,
                       int2* __restrict__ cv,
                       int nq)                           // nnz / 4
{
    int i = blockIdx.x * blockDim.x + threadIdx.x;
    if (i >= nq) return;
    int4   r = __ldcs(rows4 + i);
    int4   c = __ldcs(cols4 + i);
    float4 v = __ldcs(vals4 + i);

    __half2 vv;
    int pos;
    #define PUT(RR, CC, VF)                                               \
        vv  = __half2half2(__float2half_rn(VF));                          \
        pos = atomicAdd(&cnt[RR], 1);                                     \
        if (pos < ROWCAP)                                                 \
            cv[(long long)(RR) * ROWCAP + pos] =                          \
                make_int2((CC), *reinterpret_cast<int*>(&vv));
    PUT(r.x, c.x, v.x)
    PUT(r.y, c.y, v.y)
    PUT(r.z, c.z, v.z)
    PUT(r.w, c.w, v.w)
    #undef PUT
}

// ---------------- SpMM layer ------------------------------------------------
// 8 threads per row, one uint4 (8 halves) per lane.
// 4-edge unroll: fp16 HFMA2 partial sums, converted & added to fp32 master
// accumulator once per 4 edges (2 F2F + 2 FADD per edge instead of 8+8).
__global__ void __launch_bounds__(256)
k_spmm_h(const int* __restrict__ cnt, const int2* __restrict__ cv,
         const uint4* __restrict__ x, uint4* __restrict__ y)
{
    int t = blockIdx.x * blockDim.x + threadIdx.x;
    int r = t >> 3, q = t & 7;
    if (r >= NNODES) return;
    int n = min(__ldg(cnt + r), ROWCAP);
    const int4* row4 = reinterpret_cast<const int4*>(cv + (long long)r * ROWCAP);

    float acc[8] = {0.f, 0.f, 0.f, 0.f, 0.f, 0.f, 0.f, 0.f};

    int k = 0;
    for (; k + 3 < n; k += 4) {
        int4 e01 = __ldg(row4 + (k >> 1));
        int4 e23 = __ldg(row4 + (k >> 1) + 1);
        uint4 h0 = __ldg(x + e01.x * 8 + q);
        uint4 h1 = __ldg(x + e01.z * 8 + q);
        uint4 h2 = __ldg(x + e23.x * 8 + q);
        uint4 h3 = __ldg(x + e23.z * 8 + q);
        __half2 v0 = u2h2((unsigned)e01.y);
        __half2 v1 = u2h2((unsigned)e01.w);
        __half2 v2 = u2h2((unsigned)e23.y);
        __half2 v3 = u2h2((unsigned)e23.w);

        #define COMP(C, J)                                                 \
        {                                                                  \
            __half2 p = __hmul2(u2h2(h0.C), v0);                           \
            p = __hfma2(u2h2(h1.C), v1, p);                                \
            p = __hfma2(u2h2(h2.C), v2, p);                                \
            p = __hfma2(u2h2(h3.C), v3, p);                                \
            float2 pf = __half22float2(p);                                 \
            acc[2*(J)]     += pf.x;                                        \
            acc[2*(J) + 1] += pf.y;                                        \
        }
        COMP(x, 0)
        COMP(y, 1)
        COMP(z, 2)
        COMP(w, 3)
        #undef COMP
    }
    // tail (<=3 edges): fp32 path
    for (; k < n; ++k) {
        int2 c0 = __ldg(cv + (long long)r * ROWCAP + k);
        uint4 h0 = __ldg(x + c0.x * 8 + q);
        float v0 = __low2float(u2h2((unsigned)c0.y));
        float f0[8];
        h8_to_f8(h0, f0);
        #pragma unroll
        for (int j = 0; j < 8; ++j)
            acc[j] += v0 * f0[j];
    }

    y[r * 8 + q] = f8_to_h8(acc);
}

// ---------------- fused layer-3 + layer-mean at batch nodes ----------------
// 8 threads per slot: acc = x0(fp32 tables) + x1 + x2 + (A x2)[node]
__global__ void __launch_bounds__(256)
k_acc3(const int* __restrict__ cnt, const int2* __restrict__ cv,
       const float4* __restrict__ ut, const float4* __restrict__ it,
       const uint4* __restrict__ x1h, const uint4* __restrict__ x2h,
       const int* __restrict__ uid, const int* __restrict__ pid,
       const int* __restrict__ nid, float4* __restrict__ accb)
{
    int t = blockIdx.x * blockDim.x + threadIdx.x;
    int slot = t >> 3, q = t & 7;
    if (slot >= 3 * BATCHN) return;

    int node;
    if (slot < BATCHN) {
        node = min(max(uid[slot], 0), USERNUM);
    } else if (slot < 2 * BATCHN) {
        node = USERNUM + min(max(pid[slot - BATCHN], 1), ITEMNUM);
    } else {
        node = USERNUM + min(max(nid[slot - 2 * BATCHN], 1), ITEMNUM);
    }

    // x0 from exact fp32 tables
    const float4* x0p = (node <= USERNUM)
        ? ut + (long long)node * 16
        : it + (long long)(node - USERNUM) * 16;
    float4 f0 = __ldg(x0p + q * 2);
    float4 f1 = __ldg(x0p + q * 2 + 1);
    float acc[8] = {f0.x, f0.y, f0.z, f0.w, f1.x, f1.y, f1.z, f1.w};

    // + x1 + x2 (fp16)
    {
        float a1[8], a2[8];
        h8_to_f8(__ldg(x1h + node * 8 + q), a1);
        h8_to_f8(__ldg(x2h + node * 8 + q), a2);
        #pragma unroll
        for (int j = 0; j < 8; ++j)
            acc[j] += a1[j] + a2[j];
    }

    // + x3 = (A x2)[node]  (fp32 accumulate, weight stored as half2)
    int n = min(__ldg(cnt + node), ROWCAP);
    const int2* row = cv + (long long)node * ROWCAP;
    for (int k = 0; k < n; ++k) {
        int2 c0 = __ldg(row + k);
        float v0 = __low2float(u2h2((unsigned)c0.y));
        float f[8];
        h8_to_f8(__ldg(x2h + c0.x * 8 + q), f);
        #pragma unroll
        for (int j = 0; j < 8; ++j)
            acc[j] += v0 * f[j];
    }

    float4* dst = accb + (long long)slot * 16 + q * 2;
    dst[0] = make_float4(acc[0], acc[1], acc[2], acc[3]);
    dst[1] = make_float4(acc[4], acc[5], acc[6], acc[7]);
}

// ---------------- logits ----------------
__global__ void k_logits(const float* __restrict__ accb, float* __restrict__ out)
{
    int gt   = blockIdx.x * blockDim.x + threadIdx.x;
    int w    = gt >> 5;
    int lane = gt & 31;
    if (w >= BATCHN) return;

    const float2* ur = (const float2*)(accb + (long long)w * EMBED_D);
    const float2* pr = (const float2*)(accb + (long long)(BATCHN + w) * EMBED_D);
    const float2* nr = (const float2*)(accb + (long long)(2 * BATCHN + w) * EMBED_D);

    float2 ue = ur[lane];
    float2 pe = pr[lane];
    float2 ne = nr[lane];

    float dp = ue.x * pe.x + ue.y * pe.y;
    float dn = ue.x * ne.x + ue.y * ne.y;

    #pragma unroll
    for (int o = 16; o > 0; o >>= 1) {
        dp += __shfl_xor_sync(0xFFFFFFFFu, dp, o);
        dn += __shfl_xor_sync(0xFFFFFFFFu, dn, o);
    }
    if (lane == 0) {
        out[w]          = dp * (1.0f / 16.0f);
        out[BATCHN + w] = dn * (1.0f / 16.0f);
    }
}

// ---------------- launch ----------------
extern "C" void kernel_launch(void* const* d_in, const int* in_sizes, int n_in,
                              void* d_out, int out_size)
{
    const float* ut   = (const float*)d_in[0];   // user_table [100001, 64]
    const float* it   = (const float*)d_in[1];   // item_table [50001, 64]
    const float* vals = (const float*)d_in[2];   // [4M]
    const int*   rows = (const int*)  d_in[3];   // [4M]
    const int*   cols = (const int*)  d_in[4];   // [4M]
    const int*   uids = (const int*)  d_in[5];   // [4096]
    const int*   pids = (const int*)  d_in[6];
    const int*   nids = (const int*)  d_in[7];
    float* out = (float*)d_out;                  // [8192]: pos then neg

    __half *x0h, *x1h, *x2h;
    float* accb;
    int2* cv;
    int* cnt;
    cudaGetSymbolAddress((void**)&x0h,  g_x0h);
    cudaGetSymbolAddress((void**)&x1h,  g_x1h);
    cudaGetSymbolAddress((void**)&x2h,  g_x2h);
    cudaGetSymbolAddress((void**)&cv,   g_cv);
    cudaGetSymbolAddress((void**)&cnt,  g_cnt);
    cudaGetSymbolAddress((void**)&accb, g_accb);

    const int nblk_row8 = (NNODES * 8 + 255) / 256;      // 4,688
    const int nq = in_sizes[2] / 4;                      // nnz / 4 = 1,000,000

    // prep (fp16 x0 + cnt=0), then bucket fill
    k_prep<<<nblk_row8, 256>>>((const float4*)ut, (const float4*)it,
                               (uint4*)x0h, cnt);
    k_fill<<<(nq + 255) / 256, 256>>>((const int4*)rows, (const int4*)cols,
                                      (const float4*)vals, cnt, cv, nq);

    // layer 1: x1 = A x0
    k_spmm_h<<<nblk_row8, 256>>>(cnt, cv, (const uint4*)x0h, (uint4*)x1h);
    // layer 2: x2 = A x1
    k_spmm_h<<<nblk_row8, 256>>>(cnt, cv, (const uint4*)x1h, (uint4*)x2h);

    // layer 3 + layer-mean at batch nodes
    k_acc3<<<(3 * BATCHN * 8 + 255) / 256, 256>>>(
        cnt, cv, (const float4*)ut, (const float4*)it,
        (const uint4*)x1h, (const uint4*)x2h,
        uids, pids, nids, (float4*)accb);

    k_logits<<<(BATCHN * 32 + 255) / 256, 256>>>(accb, out);
}

// round 16
// speedup vs baseline: 1.0730x; 1.0730x over previous
#include <cuda_runtime.h>
#include <cuda_fp16.h>
#include <cuda_bf16.h>

// ---------------- problem constants ----------------
#define USERNUM   100000
#define ITEMNUM   50000
#define EMBED_D   64
#define NNODES    (USERNUM + ITEMNUM + 1)     // 150001
#define NNZ       4000000
#define BATCHN    4096
#define ROWCAP    128                         // bucket capacity per row (max deg ~66)

// ---------------- scratch (no allocs allowed) ----------------
// fp16 node-embedding buffers: 64 halves = 128 B per row (8 uint4 per row)
__device__ __align__(256) static __half g_x0h[NNODES * EMBED_D];
__device__ __align__(256) static __half g_x1h[NNODES * EMBED_D];
__device__ __align__(256) static __half g_x2h[NNODES * EMBED_D];
// padded bucket CSR: row r owns slots [r*ROWCAP, r*ROWCAP+cnt[r])
// entry = {col:int, weight: fp32 bits}
__device__ __align__(256) static int2  g_cv[(long long)NNODES * ROWCAP];
__device__ static int g_cnt[NNODES];
__device__ __align__(256) static float g_accb[3 * BATCHN * EMBED_D];

// ---------------- helpers ----------------
__device__ __forceinline__ void h8_to_f8(const uint4 h, float* f)
{
    float2 a = __half22float2(*reinterpret_cast<const __half2*>(&h.x));
    float2 b = __half22float2(*reinterpret_cast<const __half2*>(&h.y));
    float2 c = __half22float2(*reinterpret_cast<const __half2*>(&h.z));
    float2 d = __half22float2(*reinterpret_cast<const __half2*>(&h.w));
    f[0] = a.x; f[1] = a.y; f[2] = b.x; f[3] = b.y;
    f[4] = c.x; f[5] = c.y; f[6] = d.x; f[7] = d.y;
}

__device__ __forceinline__ uint4 f8_to_h8(const float* f)
{
    __half2 a = __floats2half2_rn(f[0], f[1]);
    __half2 b = __floats2half2_rn(f[2], f[3]);
    __half2 c = __floats2half2_rn(f[4], f[5]);
    __half2 d = __floats2half2_rn(f[6], f[7]);
    uint4 o;
    o.x = *reinterpret_cast<unsigned*>(&a);
    o.y = *reinterpret_cast<unsigned*>(&b);
    o.z = *reinterpret_cast<unsigned*>(&c);
    o.w = *reinterpret_cast<unsigned*>(&d);
    return o;
}

// ---------------- prep: x0h = fp16(concat(ut, it[1:]));  cnt = 0 ----------------
__global__ void k_prep(const float4* __restrict__ ut,
                       const float4* __restrict__ it,
                       uint4* __restrict__ x0h,
                       int* __restrict__ cnt)
{
    int i = blockIdx.x * blockDim.x + threadIdx.x;      // [0, NNODES*8)
    if (i >= NNODES * 8) return;
    if (i < NNODES) cnt[i] = 0;
    int node = i >> 3, q = i & 7;
    const float4* src = (node <= USERNUM)
        ? ut + (long long)node * 16
        : it + (long long)(node - USERNUM) * 16;
    float4 f0 = __ldg(src + q * 2);
    float4 f1 = __ldg(src + q * 2 + 1);
    float f[8] = {f0.x, f0.y, f0.z, f0.w, f1.x, f1.y, f1.z, f1.w};
    x0h[i] = f8_to_h8(f);
}

// ---------------- bucket fill: 4 edges/thread, vectorized streams ----------
__global__ void k_fill(const int4*   __restrict__ rows4,
                       const int4*   __restrict__ cols4,
                       const int4*   __restrict__ vals4,   // fp32 bits
                       int* __restrict__ cnt,
                       int2* __restrict__ cv,
                       int nq)                             // nnz / 4
{
    int i = blockIdx.x * blockDim.x + threadIdx.x;
    if (i >= nq) return;
    int4 r = __ldcs(rows4 + i);
    int4 c = __ldcs(cols4 + i);
    int4 v = __ldcs(vals4 + i);

    int pos;
    #define PUT(RR, CC, VB)                                               \
        pos = atomicAdd(&cnt[RR], 1);                                     \
        if (pos < ROWCAP)                                                 \
            cv[(long long)(RR) * ROWCAP + pos] = make_int2((CC), (VB));
    PUT(r.x, c.x, v.x)
    PUT(r.y, c.y, v.y)
    PUT(r.z, c.z, v.z)
    PUT(r.w, c.w, v.w)
    #undef PUT
}

// ---------------- SpMM layer ------------------------------------------------
// 8 threads per row, one uint4 (8 halves) per lane.
// 2-edge loop: ONE int4 cv load + two independent x gathers; fp32 FFMA.
// launch_bounds(256, 8): cap regs at 32 -> 8 blocks/SM for latency hiding.
__global__ void __launch_bounds__(256, 8)
k_spmm_h(const int* __restrict__ cnt, const int2* __restrict__ cv,
         const uint4* __restrict__ x, uint4* __restrict__ y)
{
    int t = blockIdx.x * blockDim.x + threadIdx.x;
    int r = t >> 3, q = t & 7;
    if (r >= NNODES) return;
    int n = min(__ldg(cnt + r), ROWCAP);
    const int4* row4 = reinterpret_cast<const int4*>(cv + (long long)r * ROWCAP);

    float acc[8] = {0.f, 0.f, 0.f, 0.f, 0.f, 0.f, 0.f, 0.f};

    int k = 0;
    for (; k + 1 < n; k += 2) {
        int4 e = __ldg(row4 + (k >> 1));          // 2 edges: {c0,v0,c1,v1}
        uint4 h0 = __ldg(x + e.x * 8 + q);
        uint4 h1 = __ldg(x + e.z * 8 + q);
        float v0 = __int_as_float(e.y), v1 = __int_as_float(e.w);
        float f0[8], f1[8];
        h8_to_f8(h0, f0);
        h8_to_f8(h1, f1);
        #pragma unroll
        for (int j = 0; j < 8; ++j)
            acc[j] += v0 * f0[j] + v1 * f1[j];
    }
    if (k < n) {
        int2 c0 = __ldg(cv + (long long)r * ROWCAP + k);
        uint4 h0 = __ldg(x + c0.x * 8 + q);
        float v0 = __int_as_float(c0.y);
        float f0[8];
        h8_to_f8(h0, f0);
        #pragma unroll
        for (int j = 0; j < 8; ++j)
            acc[j] += v0 * f0[j];
    }

    y[r * 8 + q] = f8_to_h8(acc);
}

// ---------------- fused layer-3 + layer-mean at batch nodes ----------------
// 8 threads per slot: acc = x0(fp32 tables) + x1 + x2 + (A x2)[node]
__global__ void __launch_bounds__(256)
k_acc3(const int* __restrict__ cnt, const int2* __restrict__ cv,
       const float4* __restrict__ ut, const float4* __restrict__ it,
       const uint4* __restrict__ x1h, const uint4* __restrict__ x2h,
       const int* __restrict__ uid, const int* __restrict__ pid,
       const int* __restrict__ nid, float4* __restrict__ accb)
{
    int t = blockIdx.x * blockDim.x + threadIdx.x;
    int slot = t >> 3, q = t & 7;
    if (slot >= 3 * BATCHN) return;

    int node;
    if (slot < BATCHN) {
        node = min(max(uid[slot], 0), USERNUM);
    } else if (slot < 2 * BATCHN) {
        node = USERNUM + min(max(pid[slot - BATCHN], 1), ITEMNUM);
    } else {
        node = USERNUM + min(max(nid[slot - 2 * BATCHN], 1), ITEMNUM);
    }

    // x0 from exact fp32 tables
    const float4* x0p = (node <= USERNUM)
        ? ut + (long long)node * 16
        : it + (long long)(node - USERNUM) * 16;
    float4 f0 = __ldg(x0p + q * 2);
    float4 f1 = __ldg(x0p + q * 2 + 1);
    float acc[8] = {f0.x, f0.y, f0.z, f0.w, f1.x, f1.y, f1.z, f1.w};

    // + x1 + x2 (fp16)
    {
        float a1[8], a2[8];
        h8_to_f8(__ldg(x1h + node * 8 + q), a1);
        h8_to_f8(__ldg(x2h + node * 8 + q), a2);
        #pragma unroll
        for (int j = 0; j < 8; ++j)
            acc[j] += a1[j] + a2[j];
    }

    // + x3 = (A x2)[node]
    int n = min(__ldg(cnt + node), ROWCAP);
    const int2* row = cv + (long long)node * ROWCAP;
    for (int k = 0; k < n; ++k) {
        int2 c0 = __ldg(row + k);
        float v0 = __int_as_float(c0.y);
        float f[8];
        h8_to_f8(__ldg(x2h + c0.x * 8 + q), f);
        #pragma unroll
        for (int j = 0; j < 8; ++j)
            acc[j] += v0 * f[j];
    }

    float4* dst = accb + (long long)slot * 16 + q * 2;
    dst[0] = make_float4(acc[0], acc[1], acc[2], acc[3]);
    dst[1] = make_float4(acc[4], acc[5], acc[6], acc[7]);
}

// ---------------- logits ----------------
__global__ void k_logits(const float* __restrict__ accb, float* __restrict__ out)
{
    int gt   = blockIdx.x * blockDim.x + threadIdx.x;
    int w    = gt >> 5;
    int lane = gt & 31;
    if (w >= BATCHN) return;

    const float2* ur = (const float2*)(accb + (long long)w * EMBED_D);
    const float2* pr = (const float2*)(accb + (long long)(BATCHN + w) * EMBED_D);
    const float2* nr = (const float2*)(accb + (long long)(2 * BATCHN + w) * EMBED_D);

    float2 ue = ur[lane];
    float2 pe = pr[lane];
    float2 ne = nr[lane];

    float dp = ue.x * pe.x + ue.y * pe.y;
    float dn = ue.x * ne.x + ue.y * ne.y;

    #pragma unroll
    for (int o = 16; o > 0; o >>= 1) {
        dp += __shfl_xor_sync(0xFFFFFFFFu, dp, o);
        dn += __shfl_xor_sync(0xFFFFFFFFu, dn, o);
    }
    if (lane == 0) {
        out[w]          = dp * (1.0f / 16.0f);
        out[BATCHN + w] = dn * (1.0f / 16.0f);
    }
}

// ---------------- launch ----------------
extern "C" void kernel_launch(void* const* d_in, const int* in_sizes, int n_in,
                              void* d_out, int out_size)
{
    const float* ut   = (const float*)d_in[0];   // user_table [100001, 64]
    const float* it   = (const float*)d_in[1];   // item_table [50001, 64]
    const float* vals = (const float*)d_in[2];   // [4M]
    const int*   rows = (const int*)  d_in[3];   // [4M]
    const int*   cols = (const int*)  d_in[4];   // [4M]
    const int*   uids = (const int*)  d_in[5];   // [4096]
    const int*   pids = (const int*)  d_in[6];
    const int*   nids = (const int*)  d_in[7];
    float* out = (float*)d_out;                  // [8192]: pos then neg

    __half *x0h, *x1h, *x2h;
    float* accb;
    int2* cv;
    int* cnt;
    cudaGetSymbolAddress((void**)&x0h,  g_x0h);
    cudaGetSymbolAddress((void**)&x1h,  g_x1h);
    cudaGetSymbolAddress((void**)&x2h,  g_x2h);
    cudaGetSymbolAddress((void**)&cv,   g_cv);
    cudaGetSymbolAddress((void**)&cnt,  g_cnt);
    cudaGetSymbolAddress((void**)&accb, g_accb);

    const int nblk_row8 = (NNODES * 8 + 255) / 256;      // 4,688
    const int nq = in_sizes[2] / 4;                      // nnz / 4 = 1,000,000

    // prep (fp16 x0 + cnt=0), then bucket fill
    k_prep<<<nblk_row8, 256>>>((const float4*)ut, (const float4*)it,
                               (uint4*)x0h, cnt);
    k_fill<<<(nq + 255) / 256, 256>>>((const int4*)rows, (const int4*)cols,
                                      (const int4*)vals, cnt, cv, nq);

    // layer 1: x1 = A x0
    k_spmm_h<<<nblk_row8, 256>>>(cnt, cv, (const uint4*)x0h, (uint4*)x1h);
    // layer 2: x2 = A x1
    k_spmm_h<<<nblk_row8, 256>>>(cnt, cv, (const uint4*)x1h, (uint4*)x2h);

    // layer 3 + layer-mean at batch nodes
    k_acc3<<<(3 * BATCHN * 8 + 255) / 256, 256>>>(
        cnt, cv, (const float4*)ut, (const float4*)it,
        (const uint4*)x1h, (const uint4*)x2h,
        uids, pids, nids, (float4*)accb);

    k_logits<<<(BATCHN * 32 + 255) / 256, 256>>>(accb, out);
}

// round 17
// speedup vs baseline: 1.1328x; 1.0557x over previous
#include <cuda_runtime.h>
#include <cuda_fp16.h>
#include <cuda_bf16.h>

// ---------------- problem constants ----------------
#define USERNUM   100000
#define ITEMNUM   50000
#define EMBED_D   64
#define NNODES    (USERNUM + ITEMNUM + 1)     // 150001
#define NNZ       4000000
#define BATCHN    4096
#define ROWCAP    128                         // bucket capacity per row (max deg ~66)

// ---------------- scratch (no allocs allowed) ----------------
// fp16 node-embedding buffers: 64 halves = 128 B per row (8 uint4 per row)
__device__ __align__(256) static __half g_x0h[NNODES * EMBED_D];
__device__ __align__(256) static __half g_x1h[NNODES * EMBED_D];
__device__ __align__(256) static __half g_x2h[NNODES * EMBED_D];
// padded bucket CSR: row r owns slots [r*ROWCAP, r*ROWCAP+cnt[r])
// entry = {col:int, weight: half2{v,v} bit-packed}
__device__ __align__(256) static int2  g_cv[(long long)NNODES * ROWCAP];
__device__ static int g_cnt[NNODES];
__device__ __align__(256) static float g_accb[3 * BATCHN * EMBED_D];

// ---------------- helpers ----------------
__device__ __forceinline__ void h8_to_f8(const uint4 h, float* f)
{
    float2 a = __half22float2(*reinterpret_cast<const __half2*>(&h.x));
    float2 b = __half22float2(*reinterpret_cast<const __half2*>(&h.y));
    float2 c = __half22float2(*reinterpret_cast<const __half2*>(&h.z));
    float2 d = __half22float2(*reinterpret_cast<const __half2*>(&h.w));
    f[0] = a.x; f[1] = a.y; f[2] = b.x; f[3] = b.y;
    f[4] = c.x; f[5] = c.y; f[6] = d.x; f[7] = d.y;
}

__device__ __forceinline__ uint4 f8_to_h8(const float* f)
{
    __half2 a = __floats2half2_rn(f[0], f[1]);
    __half2 b = __floats2half2_rn(f[2], f[3]);
    __half2 c = __floats2half2_rn(f[4], f[5]);
    __half2 d = __floats2half2_rn(f[6], f[7]);
    uint4 o;
    o.x = *reinterpret_cast<unsigned*>(&a);
    o.y = *reinterpret_cast<unsigned*>(&b);
    o.z = *reinterpret_cast<unsigned*>(&c);
    o.w = *reinterpret_cast<unsigned*>(&d);
    return o;
}

__device__ __forceinline__ __half2 u2h2(unsigned u)
{
    return *reinterpret_cast<__half2*>(&u);
}

// ---------------- prep: x0h = fp16(concat(ut, it[1:]));  cnt = 0 ----------------
__global__ void k_prep(const float4* __restrict__ ut,
                       const float4* __restrict__ it,
                       uint4* __restrict__ x0h,
                       int* __restrict__ cnt)
{
    int i = blockIdx.x * blockDim.x + threadIdx.x;      // [0, NNODES*8)
    if (i >= NNODES * 8) return;
    if (i < NNODES) cnt[i] = 0;
    int node = i >> 3, q = i & 7;
    const float4* src = (node <= USERNUM)
        ? ut + (long long)node * 16
        : it + (long long)(node - USERNUM) * 16;
    float4 f0 = __ldg(src + q * 2);
    float4 f1 = __ldg(src + q * 2 + 1);
    float f[8] = {f0.x, f0.y, f0.z, f0.w, f1.x, f1.y, f1.z, f1.w};
    x0h[i] = f8_to_h8(f);
}

// ---------------- bucket fill: 4 edges/thread, weight pre-splat to half2 ----
__global__ void k_fill(const int4*   __restrict__ rows4,
                       const int4*   __restrict__ cols4,
                       const float4* __restrict__ vals4,
                       int* __restrict__ cnt,
                       int2* __restrict__ cv,
                       int nq)                             // nnz / 4
{
    int i = blockIdx.x * blockDim.x + threadIdx.x;
    if (i >= nq) return;
    int4   r = __ldcs(rows4 + i);
    int4   c = __ldcs(cols4 + i);
    float4 v = __ldcs(vals4 + i);

    __half2 vv;
    int pos;
    #define PUT(RR, CC, VF)                                               \
        vv  = __half2half2(__float2half_rn(VF));                          \
        pos = atomicAdd(&cnt[RR], 1);                                     \
        if (pos < ROWCAP)                                                 \
            cv[(long long)(RR) * ROWCAP + pos] =                          \
                make_int2((CC), *reinterpret_cast<int*>(&vv));
    PUT(r.x, c.x, v.x)
    PUT(r.y, c.y, v.y)
    PUT(r.z, c.z, v.z)
    PUT(r.w, c.w, v.w)
    #undef PUT
}

// ---------------- SpMM layer ------------------------------------------------
// 8 threads per row, one uint4 (8 halves) per lane.
// 2-edge loop: ONE int4 cv load + two independent x gathers.
// fp16 2-term pairing (HMUL2+HFMA2) then one convert + fp32 add per pair:
// F2F count halved vs scalar path; staging stays at 8 regs (vs R13's 16).
__global__ void __launch_bounds__(256, 8)
k_spmm_h(const int* __restrict__ cnt, const int2* __restrict__ cv,
         const uint4* __restrict__ x, uint4* __restrict__ y)
{
    int t = blockIdx.x * blockDim.x + threadIdx.x;
    int r = t >> 3, q = t & 7;
    if (r >= NNODES) return;
    int n = min(__ldg(cnt + r), ROWCAP);
    const int4* row4 = reinterpret_cast<const int4*>(cv + (long long)r * ROWCAP);

    float acc[8] = {0.f, 0.f, 0.f, 0.f, 0.f, 0.f, 0.f, 0.f};

    int k = 0;
    for (; k + 1 < n; k += 2) {
        int4 e = __ldg(row4 + (k >> 1));          // 2 edges: {c0,v0h2,c1,v1h2}
        uint4 h0 = __ldg(x + e.x * 8 + q);
        uint4 h1 = __ldg(x + e.z * 8 + q);
        __half2 v0 = u2h2((unsigned)e.y);
        __half2 v1 = u2h2((unsigned)e.w);

        #define COMP(C, J)                                                 \
        {                                                                  \
            __half2 p = __hfma2(u2h2(h1.C), v1, __hmul2(u2h2(h0.C), v0));  \
            float2 pf = __half22float2(p);                                 \
            acc[2*(J)]     += pf.x;                                        \
            acc[2*(J) + 1] += pf.y;                                        \
        }
        COMP(x, 0)
        COMP(y, 1)
        COMP(z, 2)
        COMP(w, 3)
        #undef COMP
    }
    if (k < n) {
        int2 c0 = __ldg(cv + (long long)r * ROWCAP + k);
        uint4 h0 = __ldg(x + c0.x * 8 + q);
        float v0 = __low2float(u2h2((unsigned)c0.y));
        float f0[8];
        h8_to_f8(h0, f0);
        #pragma unroll
        for (int j = 0; j < 8; ++j)
            acc[j] += v0 * f0[j];
    }

    y[r * 8 + q] = f8_to_h8(acc);
}

// ---------------- fused layer-3 + layer-mean at batch nodes ----------------
// 8 threads per slot: acc = x0(fp32 tables) + x1 + x2 + (A x2)[node]
__global__ void __launch_bounds__(256)
k_acc3(const int* __restrict__ cnt, const int2* __restrict__ cv,
       const float4* __restrict__ ut, const float4* __restrict__ it,
       const uint4* __restrict__ x1h, const uint4* __restrict__ x2h,
       const int* __restrict__ uid, const int* __restrict__ pid,
       const int* __restrict__ nid, float4* __restrict__ accb)
{
    int t = blockIdx.x * blockDim.x + threadIdx.x;
    int slot = t >> 3, q = t & 7;
    if (slot >= 3 * BATCHN) return;

    int node;
    if (slot < BATCHN) {
        node = min(max(uid[slot], 0), USERNUM);
    } else if (slot < 2 * BATCHN) {
        node = USERNUM + min(max(pid[slot - BATCHN], 1), ITEMNUM);
    } else {
        node = USERNUM + min(max(nid[slot - 2 * BATCHN], 1), ITEMNUM);
    }

    // x0 from exact fp32 tables
    const float4* x0p = (node <= USERNUM)
        ? ut + (long long)node * 16
        : it + (long long)(node - USERNUM) * 16;
    float4 f0 = __ldg(x0p + q * 2);
    float4 f1 = __ldg(x0p + q * 2 + 1);
    float acc[8] = {f0.x, f0.y, f0.z, f0.w, f1.x, f1.y, f1.z, f1.w};

    // + x1 + x2 (fp16)
    {
        float a1[8], a2[8];
        h8_to_f8(__ldg(x1h + node * 8 + q), a1);
        h8_to_f8(__ldg(x2h + node * 8 + q), a2);
        #pragma unroll
        for (int j = 0; j < 8; ++j)
            acc[j] += a1[j] + a2[j];
    }

    // + x3 = (A x2)[node]  (fp32 accumulate)
    int n = min(__ldg(cnt + node), ROWCAP);
    const int2* row = cv + (long long)node * ROWCAP;
    for (int k = 0; k < n; ++k) {
        int2 c0 = __ldg(row + k);
        float v0 = __low2float(u2h2((unsigned)c0.y));
        float f[8];
        h8_to_f8(__ldg(x2h + c0.x * 8 + q), f);
        #pragma unroll
        for (int j = 0; j < 8; ++j)
            acc[j] += v0 * f[j];
    }

    float4* dst = accb + (long long)slot * 16 + q * 2;
    dst[0] = make_float4(acc[0], acc[1], acc[2], acc[3]);
    dst[1] = make_float4(acc[4], acc[5], acc[6], acc[7]);
}

// ---------------- logits ----------------
__global__ void k_logits(const float* __restrict__ accb, float* __restrict__ out)
{
    int gt   = blockIdx.x * blockDim.x + threadIdx.x;
    int w    = gt >> 5;
    int lane = gt & 31;
    if (w >= BATCHN) return;

    const float2* ur = (const float2*)(accb + (long long)w * EMBED_D);
    const float2* pr = (const float2*)(accb + (long long)(BATCHN + w) * EMBED_D);
    const float2* nr = (const float2*)(accb + (long long)(2 * BATCHN + w) * EMBED_D);

    float2 ue = ur[lane];
    float2 pe = pr[lane];
    float2 ne = nr[lane];

    float dp = ue.x * pe.x + ue.y * pe.y;
    float dn = ue.x * ne.x + ue.y * ne.y;

    #pragma unroll
    for (int o = 16; o > 0; o >>= 1) {
        dp += __shfl_xor_sync(0xFFFFFFFFu, dp, o);
        dn += __shfl_xor_sync(0xFFFFFFFFu, dn, o);
    }
    if (lane == 0) {
        out[w]          = dp * (1.0f / 16.0f);
        out[BATCHN + w] = dn * (1.0f / 16.0f);
    }
}

// ---------------- launch ----------------
extern "C" void kernel_launch(void* const* d_in, const int* in_sizes, int n_in,
                              void* d_out, int out_size)
{
    const float* ut   = (const float*)d_in[0];   // user_table [100001, 64]
    const float* it   = (const float*)d_in[1];   // item_table [50001, 64]
    const float* vals = (const float*)d_in[2];   // [4M]
    const int*   rows = (const int*)  d_in[3];   // [4M]
    const int*   cols = (const int*)  d_in[4];   // [4M]
    const int*   uids = (const int*)  d_in[5];   // [4096]
    const int*   pids = (const int*)  d_in[6];
    const int*   nids = (const int*)  d_in[7];
    float* out = (float*)d_out;                  // [8192]: pos then neg

    __half *x0h, *x1h, *x2h;
    float* accb;
    int2* cv;
    int* cnt;
    cudaGetSymbolAddress((void**)&x0h,  g_x0h);
    cudaGetSymbolAddress((void**)&x1h,  g_x1h);
    cudaGetSymbolAddress((void**)&x2h,  g_x2h);
    cudaGetSymbolAddress((void**)&cv,   g_cv);
    cudaGetSymbolAddress((void**)&cnt,  g_cnt);
    cudaGetSymbolAddress((void**)&accb, g_accb);

    const int nblk_row8 = (NNODES * 8 + 255) / 256;      // 4,688
    const int nq = in_sizes[2] / 4;                      // nnz / 4 = 1,000,000

    // prep (fp16 x0 + cnt=0), then bucket fill
    k_prep<<<nblk_row8, 256>>>((const float4*)ut, (const float4*)it,
                               (uint4*)x0h, cnt);
    k_fill<<<(nq + 255) / 256, 256>>>((const int4*)rows, (const int4*)cols,
                                      (const float4*)vals, cnt, cv, nq);

    // layer 1: x1 = A x0
    k_spmm_h<<<nblk_row8, 256>>>(cnt, cv, (const uint4*)x0h, (uint4*)x1h);
    // layer 2: x2 = A x1
    k_spmm_h<<<nblk_row8, 256>>>(cnt, cv, (const uint4*)x1h, (uint4*)x2h);

    // layer 3 + layer-mean at batch nodes
    k_acc3<<<(3 * BATCHN * 8 + 255) / 256, 256>>>(
        cnt, cv, (const float4*)ut, (const float4*)it,
        (const uint4*)x1h, (const uint4*)x2h,
        uids, pids, nids, (float4*)accb);

    k_logits<<<(BATCHN * 32 + 255) / 256, 256>>>(accb, out);
}